// round 15
// baseline (speedup 1.0000x reference)
#include <cuda_runtime.h>
#include <cuda_fp16.h>

typedef unsigned int u32;
typedef unsigned short u16;

#define DIMN   256
#define NHEAD  8
#define HD     32
#define BB     8
#define NQ     512
#define NK     4096
#define SCALE  0.17677669529663687f
#define QSCALE (SCALE * 1.4426950408889634f)   /* fold log2(e): softmax in exp2 domain */

// ---------------------------------------------------------------------------
// Scratch. Projection operands: fp16 hi and lo in SEPARATE arrays, permuted:
//   [row][kc*8 + (dp&3)*2 + (dp>>2)]   (dp = kpair within 16-k chunk kc)
// A thread's mma fragment half = contiguous uint2 (LDS.64).
// Attention: Q fp16 pairs; K fp16 pairs [key][perm dpair]; V fp16 pairs [key][dpair].
// ---------------------------------------------------------------------------
__device__ u32 g_sH [BB*NQ*128],          g_sL [BB*NQ*128];
__device__ u32 g_pH [BB*(size_t)NK*128],  g_pL [BB*(size_t)NK*128];
__device__ u32 g_wqH[DIMN*128],           g_wqL[DIMN*128];
__device__ u32 g_wkH[2*DIMN*128],         g_wkL[2*DIMN*128];
__device__ u32 g_woH[DIMN*128],           g_woL[DIMN*128];
__device__ u32 g_aoH[BB*NQ*128],          g_aoL[BB*NQ*128];
__device__ u32 g_qp[BB*NQ*128];                       // Q fp16 pairs (pre-scaled)
__device__ u32 g_kp[BB*NHEAD*(size_t)NK*16];          // K fp16 pairs [key][perm dpair]
__device__ u32 g_vp[BB*NHEAD*(size_t)NK*16];          // V fp16 pairs [key][dpair]

// ---------------------------------------------------------------------------
__device__ __forceinline__ void splith2(float x, float y, u32 &h, u32 &l)
{
    __half2 hv = __floats2half2_rn(x, y);
    float rx = x - __half2float(__low2half(hv));
    float ry = y - __half2float(__high2half(hv));
    __half2 lv = __floats2half2_rn(rx, ry);
    h = *reinterpret_cast<u32*>(&hv);
    l = *reinterpret_cast<u32*>(&lv);
}

__device__ __forceinline__ u32 pkh2(float x, float y)
{
    __half2 t = __floats2half2_rn(x, y);
    return *reinterpret_cast<u32*>(&t);
}

__device__ __forceinline__ u32 h2ex2(u32 s)
{
    u32 p;
    asm("ex2.approx.f16x2 %0, %1;" : "=r"(p) : "r"(s));
    return p;
}

__device__ __forceinline__ void mma_f16(float* d, u32 a0, u32 a1, u32 a2, u32 a3,
                                        u32 b0, u32 b1)
{
    asm volatile(
        "mma.sync.aligned.m16n8k16.row.col.f32.f16.f16.f32 "
        "{%0,%1,%2,%3}, {%4,%5,%6,%7}, {%8,%9}, {%0,%1,%2,%3};\n"
        : "+f"(d[0]), "+f"(d[1]), "+f"(d[2]), "+f"(d[3])
        : "r"(a0), "r"(a1), "r"(a2), "r"(a3), "r"(b0), "r"(b1));
}

__device__ __forceinline__ void ldsm4t(u32 &r0, u32 &r1, u32 &r2, u32 &r3, u32 a)
{
    asm volatile(
        "ldmatrix.sync.aligned.m8n8.x4.trans.shared.b16 {%0,%1,%2,%3}, [%4];\n"
        : "=r"(r0), "=r"(r1), "=r"(r2), "=r"(r3) : "r"(a));
}

__device__ __forceinline__ void cp16(void* smem, const void* g)
{
    u32 sa = (u32)__cvta_generic_to_shared(smem);
    asm volatile("cp.async.cg.shared.global [%0], [%1], 16;\n" :: "r"(sa), "l"(g));
}
#define CP_COMMIT() asm volatile("cp.async.commit_group;\n")
#define CP_WAIT1()  asm volatile("cp.async.wait_group 1;\n")

// ---------------------------------------------------------------------------
// Conversions. Thread handles (row, kc, j): k-pairs dp=j and dp=j+4 ->
// contiguous hi uint2 at slot 2j and lo uint2.
// ---------------------------------------------------------------------------
__global__ void conv_act_all(const float* __restrict__ state,
                             const float* __restrict__ pc)
{
    const int u = blockIdx.x * blockDim.x + threadIdx.x;
    const int row = u >> 6, j6 = u & 63;
    const int kc = j6 >> 2, j = j6 & 3;
    const float* src;
    u32 *dH, *dL;
    size_t r;
    if (row < BB * NQ) { src = state; dH = g_sH; dL = g_sL; r = row; }
    else               { src = pc;    dH = g_pH; dL = g_pL; r = row - BB * NQ; }
    const float* sp = &src[r * 256 + kc * 16 + j * 2];
    float2 f0 = *(const float2*)sp;          // k-pair dp=j
    float2 f1 = *(const float2*)(sp + 8);    // k-pair dp=j+4
    u32 h0, l0, h1, l1;
    splith2(f0.x, f0.y, h0, l0);
    splith2(f1.x, f1.y, h1, l1);
    uint2 vh = {h0, h1}, vl = {l0, l1};
    *(uint2*)&dH[r * 128 + kc * 8 + j * 2] = vh;
    *(uint2*)&dL[r * 128 + kc * 8 + j * 2] = vl;
}

__global__ __launch_bounds__(256) void conv_w_all(const float* __restrict__ Wq,
                                                  const float* __restrict__ Wkv,
                                                  const float* __restrict__ Wo)
{
    const int ntile = blockIdx.x;
    const float* W;
    u32 *dH, *dL;
    int N, n0;
    if (ntile < 8)       { W = Wq;  dH = g_wqH; dL = g_wqL; N = DIMN;     n0 = ntile * 32; }
    else if (ntile < 24) { W = Wkv; dH = g_wkH; dL = g_wkL; N = 2 * DIMN; n0 = (ntile - 8) * 32; }
    else                 { W = Wo;  dH = g_woH; dL = g_woL; N = DIMN;     n0 = (ntile - 24) * 32; }
    __shared__ float buf[64][33];
    const int k0 = blockIdx.y * 64;
    const int t = threadIdx.x;
    const int nl = t & 31, kl = t >> 5;
    #pragma unroll
    for (int r = 0; r < 8; r++)
        buf[kl + r*8][nl] = W[(size_t)(k0 + kl + r*8) * N + n0 + nl];
    __syncthreads();
    #pragma unroll
    for (int r = 0; r < 4; r++) {
        const int idx = r * 256 + t;
        const int kp = idx & 31, nn = idx >> 5;     // kp 0..31 over 64 k-rows
        const int kcl = kp >> 3, dp = kp & 7;
        const int slot = (dp & 3) * 2 + (dp >> 2);
        u32 h, l;
        splith2(buf[2*kp][nn], buf[2*kp+1][nn], h, l);
        const size_t o = (size_t)(n0 + nn) * 128 + ((k0 >> 4) + kcl) * 8 + slot;
        dH[o] = h;
        dL[o] = l;
    }
}

// ---------------------------------------------------------------------------
// GEMM: tile 256m x 64n, 256 thr (8 warps x 32m), split hi/lo stages,
// 2-stage cp.async pipeline. NP: MODE0=1; MODE1 K-cols=1, V-cols=2; MODE2=3.
// Lo stages loaded only when the pass budget needs them.
// ---------------------------------------------------------------------------
template<int MODE>
__global__ __launch_bounds__(256, 2) void gemm_pk(const float* __restrict__ bias,
                                                  float* __restrict__ C)
{
    const u32* AH = (MODE == 0) ? g_sH  : (MODE == 1) ? g_pH  : g_aoH;
    const u32* AL = (MODE == 0) ? g_sL  : (MODE == 1) ? g_pL  : g_aoL;
    const u32* WH = (MODE == 0) ? g_wqH : (MODE == 1) ? g_wkH : g_woH;
    const u32* WL = (MODE == 0) ? g_wqL : (MODE == 1) ? g_wkL : g_woL;

    __shared__ __align__(16) u32 AsH[2][256][8], AsL[2][256][8];
    __shared__ __align__(16) u32 WsH[2][64][8],  WsL[2][64][8];
    const int t = threadIdx.x, lane = t & 31, wrp = t >> 5;
    const int gid = lane >> 2, tig = lane & 3;
    const long m0 = blockIdx.y * 256L;
    const int  n0 = blockIdx.x * 64;

    const int NP = (MODE == 0) ? 1 : (MODE == 2) ? 3 : ((n0 < DIMN) ? 1 : 2);

    float acc[2][8][4] = {};

    // Stage loaders: A-hi 512 chunks (2/thread); W-hi 128 chunks (t<128).
    const int arow0 = t >> 1,          aoff0 = (t & 1) * 4;
    const int arow1 = (t + 256) >> 1,  aoff1 = (t & 1) * 4;   // rows 128..255
    const int wrow  = t >> 1,          woff  = (t & 1) * 4;

    const u32* apH0 = &AH[(m0 + arow0) * 128 + aoff0];
    const u32* apH1 = &AH[(m0 + arow1) * 128 + aoff1];
    const u32* apL0 = &AL[(m0 + arow0) * 128 + aoff0];
    const u32* apL1 = &AL[(m0 + arow1) * 128 + aoff1];
    const u32* wpH  = &WH[(size_t)(n0 + wrow) * 128 + woff];
    const u32* wpL  = &WL[(size_t)(n0 + wrow) * 128 + woff];

    {
        cp16(&AsH[0][arow0][aoff0], apH0);
        cp16(&AsH[0][arow1][aoff1], apH1);
        if (t < 128) cp16(&WsH[0][wrow][woff], wpH);
        if (NP >= 2) {
            cp16(&AsL[0][arow0][aoff0], apL0);
            cp16(&AsL[0][arow1][aoff1], apL1);
        }
        if (NP >= 3 && t < 128) cp16(&WsL[0][wrow][woff], wpL);
    }
    CP_COMMIT();

    for (int kc = 0; kc < 16; kc++) {
        const int s = kc & 1;
        if (kc + 1 < 16) {
            cp16(&AsH[s^1][arow0][aoff0], apH0 + (kc+1)*8);
            cp16(&AsH[s^1][arow1][aoff1], apH1 + (kc+1)*8);
            if (t < 128) cp16(&WsH[s^1][wrow][woff], wpH + (kc+1)*8);
            if (NP >= 2) {
                cp16(&AsL[s^1][arow0][aoff0], apL0 + (kc+1)*8);
                cp16(&AsL[s^1][arow1][aoff1], apL1 + (kc+1)*8);
            }
            if (NP >= 3 && t < 128) cp16(&WsL[s^1][wrow][woff], wpL + (kc+1)*8);
        }
        CP_COMMIT();
        CP_WAIT1();
        __syncthreads();

        const int r0 = wrp * 32 + gid;
        uint2 aH0 = *(const uint2*)&AsH[s][r0][tig * 2];       // (a0, a2)
        uint2 aH1 = *(const uint2*)&AsH[s][r0 + 8][tig * 2];   // (a1, a3)
        uint2 aH2 = *(const uint2*)&AsH[s][r0 + 16][tig * 2];
        uint2 aH3 = *(const uint2*)&AsH[s][r0 + 24][tig * 2];
        uint2 aL0, aL1, aL2, aL3;
        if (NP >= 2) {
            aL0 = *(const uint2*)&AsL[s][r0][tig * 2];
            aL1 = *(const uint2*)&AsL[s][r0 + 8][tig * 2];
            aL2 = *(const uint2*)&AsL[s][r0 + 16][tig * 2];
            aL3 = *(const uint2*)&AsL[s][r0 + 24][tig * 2];
        }
        #pragma unroll
        for (int nt = 0; nt < 8; nt++) {
            uint2 wH = *(const uint2*)&WsH[s][nt*8 + gid][tig * 2];  // (b0, b1)
            mma_f16(acc[0][nt], aH0.x, aH1.x, aH0.y, aH1.y, wH.x, wH.y);
            mma_f16(acc[1][nt], aH2.x, aH3.x, aH2.y, aH3.y, wH.x, wH.y);
            if (NP >= 2) {
                mma_f16(acc[0][nt], aL0.x, aL1.x, aL0.y, aL1.y, wH.x, wH.y);
                mma_f16(acc[1][nt], aL2.x, aL3.x, aL2.y, aL3.y, wH.x, wH.y);
            }
            if (NP >= 3) {
                uint2 wL = *(const uint2*)&WsL[s][nt*8 + gid][tig * 2];
                mma_f16(acc[0][nt], aH0.x, aH1.x, aH0.y, aH1.y, wL.x, wL.y);
                mma_f16(acc[1][nt], aH2.x, aH3.x, aH2.y, aH3.y, wL.x, wL.y);
            }
        }
        __syncthreads();
    }

    #pragma unroll
    for (int half = 0; half < 2; half++) {
        const long mrow = m0 + wrp * 32 + half * 16 + gid;
        #pragma unroll
        for (int nt = 0; nt < 8; nt++) {
            const int col = n0 + nt * 8 + 2 * tig;
            const float b0v = bias[col], b1v = bias[col + 1];
            float v00 = acc[half][nt][0] + b0v, v01 = acc[half][nt][1] + b1v;
            float v10 = acc[half][nt][2] + b0v, v11 = acc[half][nt][3] + b1v;
            if (MODE == 0) {
                g_qp[mrow*128 + (col>>1)]     = pkh2(v00 * QSCALE, v01 * QSCALE);
                g_qp[(mrow+8)*128 + (col>>1)] = pkh2(v10 * QSCALE, v11 * QSCALE);
            } else if (MODE == 2) {
                *(float2*)&C[mrow*DIMN + col]     = make_float2(v00, v01);
                *(float2*)&C[(mrow+8)*DIMN + col] = make_float2(v10, v11);
            } else {
                const int bb = (int)(mrow >> 12), key = (int)(mrow & (NK - 1));
                if (n0 < DIMN) {
                    const int hh = col >> 5, dp = (col & 31) >> 1;
                    const int pdp = (dp & 3) * 4 + (dp >> 2);
                    g_kp[((size_t)(bb*NHEAD+hh)*NK + key) * 16 + pdp]     = pkh2(v00, v01);
                    g_kp[((size_t)(bb*NHEAD+hh)*NK + key + 8) * 16 + pdp] = pkh2(v10, v11);
                } else {
                    const int c2 = col - DIMN, hh = c2 >> 5, dp = (c2 & 31) >> 1;
                    g_vp[((size_t)(bb*NHEAD+hh)*NK + key) * 16 + dp]     = pkh2(v00, v01);
                    g_vp[((size_t)(bb*NHEAD+hh)*NK + key + 8) * 16 + dp] = pkh2(v10, v11);
                }
            }
        }
    }
}

// ---------------------------------------------------------------------------
// Flash attention: 256 thr (8 warps), q-tile 128, k-tile 64, fp16 mma.
// Fixed-max softmax via ex2.approx.f16x2. V fragments via ldmatrix.x4.trans.
// ---------------------------------------------------------------------------
__device__ __forceinline__ void copy_tile(u32 (*Ks)[16], u32 (*Vs)[20],
                                          int k0, int t,
                                          size_t kbase, size_t vbase)
{
    const int row = t >> 2, off = (t & 3) * 4;
    cp16(&Ks[row][off], &g_kp[kbase + (size_t)(k0 + row) * 16 + off]);
    cp16(&Vs[row][off], &g_vp[vbase + (size_t)(k0 + row) * 16 + off]);
}

__global__ __launch_bounds__(256, 2) void attn_mma()
{
    __shared__ __align__(16) u32 KsS[2][64][16];
    __shared__ __align__(16) u32 VsS[2][64][20];   // pad 16->20: ldmatrix conflict-free

    const int t = threadIdx.x, lane = t & 31, wrp = t >> 5;
    const int gid = lane >> 2, tig = lane & 3;
    const int q0 = blockIdx.x * 128, h = blockIdx.y, b = blockIdx.z;
    const int bh = b * NHEAD + h;

    u32 qp[2][4];
    {
        const long r0 = (long)(b * NQ + q0 + wrp * 16 + gid) * 128 + h * 16;
        #pragma unroll
        for (int s = 0; s < 2; s++) {
            qp[s][0] = g_qp[r0 + s*8 + tig];
            qp[s][1] = g_qp[r0 + 1024 + s*8 + tig];
            qp[s][2] = g_qp[r0 + s*8 + tig + 4];
            qp[s][3] = g_qp[r0 + 1024 + s*8 + tig + 4];
        }
    }

    float lA = 0.f, lB = 0.f;
    float oacc[4][4] = {};

    const size_t kbase = (size_t)bh * NK * 16;
    const size_t vbase = (size_t)bh * NK * 16;

    const u32 vsm0 = (u32)__cvta_generic_to_shared(&VsS[0][0][0]) + lane * 80;

    copy_tile(KsS[0], VsS[0], 0, t, kbase, vbase);
    CP_COMMIT();

    for (int kt = 0; kt < NK / 64; kt++) {
        const int s = kt & 1;
        if (kt + 1 < NK / 64)
            copy_tile(KsS[s^1], VsS[s^1], (kt + 1) * 64, t, kbase, vbase);
        CP_COMMIT();
        CP_WAIT1();
        __syncthreads();

        // S = Q @ K^T (fp16, single pass, 2 k-steps). One LDS.128 per nt.
        float sacc[8][4] = {};
        #pragma unroll
        for (int nt = 0; nt < 8; nt++) {
            const int kr = nt * 8 + gid;
            uint4 kb = *(const uint4*)&KsS[s][kr][4 * tig];
            mma_f16(sacc[nt], qp[0][0], qp[0][1], qp[0][2], qp[0][3], kb.x, kb.y);
            mma_f16(sacc[nt], qp[1][0], qp[1][1], qp[1][2], qp[1][3], kb.z, kb.w);
        }

        // Fixed-max softmax: pack to half2, exp2 in f16x2, sum l in half2.
        u32 pha[4][4];
        __half2 sA2 = __floats2half2_rn(0.f, 0.f);
        __half2 sB2 = sA2;
        #pragma unroll
        for (int tt = 0; tt < 4; tt++) {
            #pragma unroll
            for (int u = 0; u < 2; u++) {
                const int nt = 2 * tt + u;
                u32 pa = h2ex2(pkh2(sacc[nt][0], sacc[nt][1]));
                u32 pb = h2ex2(pkh2(sacc[nt][2], sacc[nt][3]));
                pha[tt][u*2]   = pa;
                pha[tt][u*2+1] = pb;
                sA2 = __hadd2(sA2, *reinterpret_cast<__half2*>(&pa));
                sB2 = __hadd2(sB2, *reinterpret_cast<__half2*>(&pb));
            }
        }
        {
            float2 fa = __half22float2(sA2), fb = __half22float2(sB2);
            lA += fa.x + fa.y;
            lB += fb.x + fb.y;
        }

        // O += P @ V: 2 ldmatrix.x4.trans per dnt give all 4 k-step B-fragments.
        const u32 va = vsm0 + s * 5120;
        #pragma unroll
        for (int dnt = 0; dnt < 4; dnt++) {
            u32 b00, b01, b10, b11, b20, b21, b30, b31;
            ldsm4t(b00, b01, b10, b11, va + dnt * 16);          // keys 0..31
            ldsm4t(b20, b21, b30, b31, va + dnt * 16 + 2560);   // keys 32..63
            mma_f16(oacc[dnt], pha[0][0], pha[0][1], pha[0][2], pha[0][3], b00, b01);
            mma_f16(oacc[dnt], pha[1][0], pha[1][1], pha[1][2], pha[1][3], b10, b11);
            mma_f16(oacc[dnt], pha[2][0], pha[2][1], pha[2][2], pha[2][3], b20, b21);
            mma_f16(oacc[dnt], pha[3][0], pha[3][1], pha[3][2], pha[3][3], b30, b31);
        }
        __syncthreads();
    }

    lA += __shfl_xor_sync(0xffffffffu, lA, 1);
    lA += __shfl_xor_sync(0xffffffffu, lA, 2);
    lB += __shfl_xor_sync(0xffffffffu, lB, 1);
    lB += __shfl_xor_sync(0xffffffffu, lB, 2);

    const float invA = 1.f / lA, invB = 1.f / lB;
    const long orow = (long)(b * NQ + q0 + wrp * 16 + gid);
    #pragma unroll
    for (int dnt = 0; dnt < 4; dnt++) {
        const int np = h * 16 + dnt * 4 + tig;          // kpair index 0..127
        const int kc = np >> 3, dp = np & 7;
        const int slot = (dp & 3) * 2 + (dp >> 2);
        u32 hh, ll;
        splith2(oacc[dnt][0] * invA, oacc[dnt][1] * invA, hh, ll);
        g_aoH[orow*128 + kc*8 + slot] = hh;
        g_aoL[orow*128 + kc*8 + slot] = ll;
        splith2(oacc[dnt][2] * invB, oacc[dnt][3] * invB, hh, ll);
        g_aoH[(orow+8)*128 + kc*8 + slot] = hh;
        g_aoL[(orow+8)*128 + kc*8 + slot] = ll;
    }
}

// ---------------------------------------------------------------------------
extern "C" void kernel_launch(void* const* d_in, const int* in_sizes, int n_in,
                              void* d_out, int out_size)
{
    const float* state = (const float*)d_in[0];
    const float* pc    = (const float*)d_in[1];
    const float* Wq    = (const float*)d_in[2];
    const float* bq    = (const float*)d_in[3];
    const float* Wkv   = (const float*)d_in[4];
    const float* bkv   = (const float*)d_in[5];
    const float* Wo    = (const float*)d_in[6];
    const float* bo    = (const float*)d_in[7];
    float* out = (float*)d_out;

    conv_act_all<<<(BB*NQ + BB*NK) * 64 / 256, 256>>>(state, pc);
    conv_w_all<<<dim3(32, 4), 256>>>(Wq, Wkv, Wo);

    gemm_pk<0><<<dim3(DIMN/64,   BB*NQ/256), 256>>>(bq,  nullptr);
    gemm_pk<1><<<dim3(2*DIMN/64, BB*NK/256), 256>>>(bkv, nullptr);
    attn_mma<<<dim3(NQ/128, NHEAD, BB), 256>>>();
    gemm_pk<2><<<dim3(DIMN/64,   BB*NQ/256), 256>>>(bo, out);
}

// round 16
// speedup vs baseline: 1.5009x; 1.5009x over previous
#include <cuda_runtime.h>
#include <cuda_fp16.h>

typedef unsigned int u32;
typedef unsigned short u16;

#define DIMN   256
#define NHEAD  8
#define HD     32
#define BB     8
#define NQ     512
#define NK     4096
#define SCALE  0.17677669529663687f
#define QSCALE (SCALE * 1.4426950408889634f)   /* fold log2(e): softmax in exp2 domain */

// ---------------------------------------------------------------------------
// Scratch.
// Hi-only operands (state/pointcloud/Wq/Wkv): fp16 pairs, super-chunk packed:
//   [row][sc*16 + (dp&3)*4 + (dp>>2)*2 + (kc&1)]  (sc=k/32, kc=k/16, dp=kpair in kc)
//   -> one uint4 = fragment halves for TWO k-chunks.
// O-proj operands (ao/Wo): fp16 hi/lo interleaved (R14 layout):
//   [row][kc*16 + (dp&3)*4 + (dp>>2)*2 + hilo]
// Attention: Q fp16 pairs; K fp16 pairs [key][perm dpair]; V fp16 pairs [key][dpair].
// ---------------------------------------------------------------------------
__device__ u32 g_sH[BB*NQ*128];                       // state (hi only)
__device__ u32 g_pH[BB*(size_t)NK*128];               // pointcloud (hi only)
__device__ u32 g_wqH[DIMN*128];                       // Wq^T (hi only)
__device__ u32 g_wkH[2*DIMN*128];                     // Wkv^T (hi only)
__device__ u32 g_wo[DIMN*256];                        // Wo^T (hi/lo interleaved)
__device__ u32 g_ao[BB*NQ*256];                       // attention out (hi/lo interleaved)
__device__ u32 g_qp[BB*NQ*128];                       // Q fp16 pairs (pre-scaled)
__device__ u32 g_kp[BB*NHEAD*(size_t)NK*16];          // K fp16 pairs [key][perm dpair]
__device__ u32 g_vp[BB*NHEAD*(size_t)NK*16];          // V fp16 pairs [key][dpair]

// ---------------------------------------------------------------------------
__device__ __forceinline__ void splith2(float x, float y, u32 &h, u32 &l)
{
    __half2 hv = __floats2half2_rn(x, y);
    float rx = x - __half2float(__low2half(hv));
    float ry = y - __half2float(__high2half(hv));
    __half2 lv = __floats2half2_rn(rx, ry);
    h = *reinterpret_cast<u32*>(&hv);
    l = *reinterpret_cast<u32*>(&lv);
}

__device__ __forceinline__ u32 pkh2(float x, float y)
{
    __half2 t = __floats2half2_rn(x, y);
    return *reinterpret_cast<u32*>(&t);
}

__device__ __forceinline__ u32 h2ex2(u32 s)
{
    u32 p;
    asm("ex2.approx.f16x2 %0, %1;" : "=r"(p) : "r"(s));
    return p;
}

__device__ __forceinline__ void mma_f16(float* d, u32 a0, u32 a1, u32 a2, u32 a3,
                                        u32 b0, u32 b1)
{
    asm volatile(
        "mma.sync.aligned.m16n8k16.row.col.f32.f16.f16.f32 "
        "{%0,%1,%2,%3}, {%4,%5,%6,%7}, {%8,%9}, {%0,%1,%2,%3};\n"
        : "+f"(d[0]), "+f"(d[1]), "+f"(d[2]), "+f"(d[3])
        : "r"(a0), "r"(a1), "r"(a2), "r"(a3), "r"(b0), "r"(b1));
}

__device__ __forceinline__ void ldsm4t(u32 &r0, u32 &r1, u32 &r2, u32 &r3, u32 a)
{
    asm volatile(
        "ldmatrix.sync.aligned.m8n8.x4.trans.shared.b16 {%0,%1,%2,%3}, [%4];\n"
        : "=r"(r0), "=r"(r1), "=r"(r2), "=r"(r3) : "r"(a));
}

__device__ __forceinline__ void cp16(void* smem, const void* g)
{
    u32 sa = (u32)__cvta_generic_to_shared(smem);
    asm volatile("cp.async.cg.shared.global [%0], [%1], 16;\n" :: "r"(sa), "l"(g));
}
#define CP_COMMIT() asm volatile("cp.async.commit_group;\n")
#define CP_WAIT1()  asm volatile("cp.async.wait_group 1;\n")

// ---------------------------------------------------------------------------
// Conversions.
// ---------------------------------------------------------------------------
// Activations -> hi-only super-chunk layout. Thread: (row, sc, tig) -> 1 uint4.
__global__ void conv_act_all(const float* __restrict__ state,
                             const float* __restrict__ pc)
{
    const int u = blockIdx.x * blockDim.x + threadIdx.x;
    const int row = u >> 5, j = u & 31;
    const int sc = j >> 2, tig = j & 3;
    const float* src;
    u32* dst;
    size_t r;
    if (row < BB * NQ) { src = state; dst = g_sH; r = row; }
    else               { src = pc;    dst = g_pH; r = row - BB * NQ; }
    const float* sp = &src[r * 256 + sc * 32 + tig * 2];
    float2 f0 = *(const float2*)sp;          // kc0, dp=tig
    float2 f1 = *(const float2*)(sp + 8);    // kc0, dp=tig+4
    float2 f2 = *(const float2*)(sp + 16);   // kc1, dp=tig
    float2 f3 = *(const float2*)(sp + 24);   // kc1, dp=tig+4
    uint4 v;
    v.x = pkh2(f0.x, f0.y);
    v.y = pkh2(f2.x, f2.y);
    v.z = pkh2(f1.x, f1.y);
    v.w = pkh2(f3.x, f3.y);
    *(uint4*)&dst[r * 128 + sc * 16 + tig * 4] = v;
}

__global__ __launch_bounds__(256) void conv_w_all(const float* __restrict__ Wq,
                                                  const float* __restrict__ Wkv,
                                                  const float* __restrict__ Wo)
{
    const int ntile = blockIdx.x;
    const float* W;
    int N, n0, isWo = 0;
    u32* dst;
    if (ntile < 8)       { W = Wq;  dst = g_wqH; N = DIMN;     n0 = ntile * 32; }
    else if (ntile < 24) { W = Wkv; dst = g_wkH; N = 2 * DIMN; n0 = (ntile - 8) * 32; }
    else                 { W = Wo;  dst = g_wo;  N = DIMN;     n0 = (ntile - 24) * 32; isWo = 1; }
    __shared__ float buf[64][33];
    const int k0 = blockIdx.y * 64;
    const int t = threadIdx.x;
    const int nl = t & 31, kl = t >> 5;
    #pragma unroll
    for (int r = 0; r < 8; r++)
        buf[kl + r*8][nl] = W[(size_t)(k0 + kl + r*8) * N + n0 + nl];
    __syncthreads();
    #pragma unroll
    for (int r = 0; r < 4; r++) {
        const int idx = r * 256 + t;
        const int kp = idx & 31, nn = idx >> 5;     // kp local kpair 0..31
        u32 h, l;
        splith2(buf[2*kp][nn], buf[2*kp+1][nn], h, l);
        if (isWo) {
            const int kcl = kp >> 3, dp = kp & 7;
            const int slot = (dp & 3) * 4 + (dp >> 2) * 2;
            uint2 v = {h, l};
            *(uint2*)&dst[(size_t)(n0 + nn) * 256 + ((k0 >> 4) + kcl) * 16 + slot] = v;
        } else {
            const int gkp = (k0 >> 1) + kp;          // global kpair
            const int kc = gkp >> 3, dp = gkp & 7;
            const int sc = kc >> 1, kcp = kc & 1;
            dst[(size_t)(n0 + nn) * 128 + sc * 16 + (dp & 3) * 4 + (dp >> 2) * 2 + kcp] = h;
        }
    }
}

// ---------------------------------------------------------------------------
// Hi-only GEMM (NP=1): tile NH*128 m x 64 n, 256 thr (8 warps x NH*16 m),
// super-chunk stages (32 k each), 2-stage cp.async pipeline.
// MODE 0: Q-proj -> g_qp (*QSCALE), NH=1. MODE 1: KV -> K/V scatter, NH=2.
// ---------------------------------------------------------------------------
template<int MODE, int NH>
__global__ __launch_bounds__(256, 2) void gemm_hi(const float* __restrict__ bias)
{
    const u32* A = (MODE == 0) ? g_sH  : g_pH;
    const u32* W = (MODE == 0) ? g_wqH : g_wkH;

    __shared__ __align__(16) u32 As[2][NH*128][16];
    __shared__ __align__(16) u32 Ws[2][64][16];
    const int t = threadIdx.x, lane = t & 31, wrp = t >> 5;
    const int gid = lane >> 2, tig = lane & 3;
    const long m0 = blockIdx.y * (NH * 128L);
    const int  n0 = blockIdx.x * 64;

    float acc[NH][8][4] = {};
    const int arow = t >> 2, aoff = (t & 3) * 4;    // 64 rows/iter, NH*2 iters
    const int wrow = t >> 2, woff = (t & 3) * 4;

    const u32* ap = &A[(m0 + arow) * 128 + aoff];
    const u32* wp = &W[(size_t)(n0 + wrow) * 128 + woff];

    #pragma unroll
    for (int r = 0; r < NH * 2; r++)
        cp16(&As[0][arow + r * 64][aoff], ap + (size_t)r * 64 * 128);
    cp16(&Ws[0][wrow][woff], wp);
    CP_COMMIT();

    for (int sc = 0; sc < 8; sc++) {
        const int s = sc & 1;
        if (sc + 1 < 8) {
            #pragma unroll
            for (int r = 0; r < NH * 2; r++)
                cp16(&As[s^1][arow + r * 64][aoff], ap + (size_t)r * 64 * 128 + (sc+1)*16);
            cp16(&Ws[s^1][wrow][woff], wp + (sc+1)*16);
        }
        CP_COMMIT();
        CP_WAIT1();
        __syncthreads();

        const int r0 = wrp * (NH * 16) + gid;
        uint4 aA[NH], aB[NH];
        #pragma unroll
        for (int h = 0; h < NH; h++) {
            aA[h] = *(const uint4*)&As[s][r0 + h * 16][tig * 4];
            aB[h] = *(const uint4*)&As[s][r0 + h * 16 + 8][tig * 4];
        }
        #pragma unroll
        for (int nt = 0; nt < 8; nt++) {
            uint4 wv = *(const uint4*)&Ws[s][nt*8 + gid][tig * 4];
            #pragma unroll
            for (int h = 0; h < NH; h++) {
                mma_f16(acc[h][nt], aA[h].x, aB[h].x, aA[h].z, aB[h].z, wv.x, wv.z);
                mma_f16(acc[h][nt], aA[h].y, aB[h].y, aA[h].w, aB[h].w, wv.y, wv.w);
            }
        }
        __syncthreads();
    }

    #pragma unroll
    for (int h = 0; h < NH; h++) {
        const long mrow = m0 + wrp * (NH * 16) + h * 16 + gid;
        #pragma unroll
        for (int nt = 0; nt < 8; nt++) {
            const int col = n0 + nt * 8 + 2 * tig;
            const float b0v = bias[col], b1v = bias[col + 1];
            float v00 = acc[h][nt][0] + b0v, v01 = acc[h][nt][1] + b1v;
            float v10 = acc[h][nt][2] + b0v, v11 = acc[h][nt][3] + b1v;
            if (MODE == 0) {
                g_qp[mrow*128 + (col>>1)]     = pkh2(v00 * QSCALE, v01 * QSCALE);
                g_qp[(mrow+8)*128 + (col>>1)] = pkh2(v10 * QSCALE, v11 * QSCALE);
            } else {
                const int bb = (int)(mrow >> 12), key = (int)(mrow & (NK - 1));
                if (n0 < DIMN) {
                    const int hh = col >> 5, dp = (col & 31) >> 1;
                    const int pdp = (dp & 3) * 4 + (dp >> 2);
                    g_kp[((size_t)(bb*NHEAD+hh)*NK + key) * 16 + pdp]     = pkh2(v00, v01);
                    g_kp[((size_t)(bb*NHEAD+hh)*NK + key + 8) * 16 + pdp] = pkh2(v10, v11);
                } else {
                    const int c2 = col - DIMN, hh = c2 >> 5, dp = (c2 & 31) >> 1;
                    g_vp[((size_t)(bb*NHEAD+hh)*NK + key) * 16 + dp]     = pkh2(v00, v01);
                    g_vp[((size_t)(bb*NHEAD+hh)*NK + key + 8) * 16 + dp] = pkh2(v10, v11);
                }
            }
        }
    }
}

// ---------------------------------------------------------------------------
// O-proj GEMM (NP=3, hi/lo interleaved): tile 128m x 64n, 256 thr.
// ---------------------------------------------------------------------------
__global__ __launch_bounds__(256, 2) void gemm_o(const float* __restrict__ bias,
                                                 float* __restrict__ C)
{
    __shared__ __align__(16) u32 As[2][128][16];
    __shared__ __align__(16) u32 Ws[2][64][16];
    const int t = threadIdx.x, lane = t & 31, wrp = t >> 5;
    const int gid = lane >> 2, tig = lane & 3;
    const long m0 = blockIdx.y * 128L;
    const int  n0 = blockIdx.x * 64;

    float acc[8][4] = {};
    const int arow = t >> 1, aoff = (t & 1) * 8;
    const int wrow = t >> 2, woff = (t & 3) * 4;

    const u32* ap = &g_ao[(m0 + arow) * 256 + aoff];
    const u32* wp = &g_wo[(size_t)(n0 + wrow) * 256 + woff];

    cp16(&As[0][arow][aoff],     ap);
    cp16(&As[0][arow][aoff + 4], ap + 4);
    cp16(&Ws[0][wrow][woff],     wp);
    CP_COMMIT();

    for (int kc = 0; kc < 16; kc++) {
        const int s = kc & 1;
        if (kc + 1 < 16) {
            cp16(&As[s^1][arow][aoff],     ap + (kc+1)*16);
            cp16(&As[s^1][arow][aoff + 4], ap + (kc+1)*16 + 4);
            cp16(&Ws[s^1][wrow][woff],     wp + (kc+1)*16);
        }
        CP_COMMIT();
        CP_WAIT1();
        __syncthreads();

        const int r0 = wrp * 16 + gid;
        uint4 aA = *(const uint4*)&As[s][r0][tig * 4];      // (ah0, al0, ah2, al2)
        uint4 aB = *(const uint4*)&As[s][r0 + 8][tig * 4];  // (ah1, al1, ah3, al3)
        #pragma unroll
        for (int nt = 0; nt < 8; nt++) {
            uint4 wv = *(const uint4*)&Ws[s][nt*8 + gid][tig * 4]; // (bh0,bl0,bh1,bl1)
            mma_f16(acc[nt], aA.x, aB.x, aA.z, aB.z, wv.x, wv.z);
            mma_f16(acc[nt], aA.y, aB.y, aA.w, aB.w, wv.x, wv.z);
            mma_f16(acc[nt], aA.x, aB.x, aA.z, aB.z, wv.y, wv.w);
        }
        __syncthreads();
    }

    const long mrow = m0 + wrp * 16 + gid;
    #pragma unroll
    for (int nt = 0; nt < 8; nt++) {
        const int col = n0 + nt * 8 + 2 * tig;
        const float b0v = bias[col], b1v = bias[col + 1];
        *(float2*)&C[mrow*DIMN + col] =
            make_float2(acc[nt][0] + b0v, acc[nt][1] + b1v);
        *(float2*)&C[(mrow+8)*DIMN + col] =
            make_float2(acc[nt][2] + b0v, acc[nt][3] + b1v);
    }
}

// ---------------------------------------------------------------------------
// Flash attention: 256 thr (8 warps), q-tile 128, k-tile 64, fp16 mma.
// Fixed-max softmax via ex2.approx.f16x2. V fragments via ldmatrix.x4.trans.
// ---------------------------------------------------------------------------
__device__ __forceinline__ void copy_tile(u32 (*Ks)[16], u32 (*Vs)[20],
                                          int k0, int t,
                                          size_t kbase, size_t vbase)
{
    const int row = t >> 2, off = (t & 3) * 4;
    cp16(&Ks[row][off], &g_kp[kbase + (size_t)(k0 + row) * 16 + off]);
    cp16(&Vs[row][off], &g_vp[vbase + (size_t)(k0 + row) * 16 + off]);
}

__global__ __launch_bounds__(256, 2) void attn_mma()
{
    __shared__ __align__(16) u32 KsS[2][64][16];
    __shared__ __align__(16) u32 VsS[2][64][20];   // pad 16->20: ldmatrix conflict-free

    const int t = threadIdx.x, lane = t & 31, wrp = t >> 5;
    const int gid = lane >> 2, tig = lane & 3;
    const int q0 = blockIdx.x * 128, h = blockIdx.y, b = blockIdx.z;
    const int bh = b * NHEAD + h;

    u32 qp[2][4];
    {
        const long r0 = (long)(b * NQ + q0 + wrp * 16 + gid) * 128 + h * 16;
        #pragma unroll
        for (int s = 0; s < 2; s++) {
            qp[s][0] = g_qp[r0 + s*8 + tig];
            qp[s][1] = g_qp[r0 + 1024 + s*8 + tig];
            qp[s][2] = g_qp[r0 + s*8 + tig + 4];
            qp[s][3] = g_qp[r0 + 1024 + s*8 + tig + 4];
        }
    }

    float lA = 0.f, lB = 0.f;
    float oacc[4][4] = {};

    const size_t kbase = (size_t)bh * NK * 16;
    const size_t vbase = (size_t)bh * NK * 16;

    const u32 vsm0 = (u32)__cvta_generic_to_shared(&VsS[0][0][0]) + lane * 80;

    copy_tile(KsS[0], VsS[0], 0, t, kbase, vbase);
    CP_COMMIT();

    for (int kt = 0; kt < NK / 64; kt++) {
        const int s = kt & 1;
        if (kt + 1 < NK / 64)
            copy_tile(KsS[s^1], VsS[s^1], (kt + 1) * 64, t, kbase, vbase);
        CP_COMMIT();
        CP_WAIT1();
        __syncthreads();

        // S = Q @ K^T (fp16, single pass, 2 k-steps). One LDS.128 per nt.
        float sacc[8][4] = {};
        #pragma unroll
        for (int nt = 0; nt < 8; nt++) {
            const int kr = nt * 8 + gid;
            uint4 kb = *(const uint4*)&KsS[s][kr][4 * tig];
            mma_f16(sacc[nt], qp[0][0], qp[0][1], qp[0][2], qp[0][3], kb.x, kb.y);
            mma_f16(sacc[nt], qp[1][0], qp[1][1], qp[1][2], qp[1][3], kb.z, kb.w);
        }

        // Fixed-max softmax: pack to half2, exp2 in f16x2, sum l in half2.
        u32 pha[4][4];
        __half2 sA2 = __floats2half2_rn(0.f, 0.f);
        __half2 sB2 = sA2;
        #pragma unroll
        for (int tt = 0; tt < 4; tt++) {
            #pragma unroll
            for (int u = 0; u < 2; u++) {
                const int nt = 2 * tt + u;
                u32 pa = h2ex2(pkh2(sacc[nt][0], sacc[nt][1]));
                u32 pb = h2ex2(pkh2(sacc[nt][2], sacc[nt][3]));
                pha[tt][u*2]   = pa;
                pha[tt][u*2+1] = pb;
                sA2 = __hadd2(sA2, *reinterpret_cast<__half2*>(&pa));
                sB2 = __hadd2(sB2, *reinterpret_cast<__half2*>(&pb));
            }
        }
        {
            float2 fa = __half22float2(sA2), fb = __half22float2(sB2);
            lA += fa.x + fa.y;
            lB += fb.x + fb.y;
        }

        // O += P @ V: 2 ldmatrix.x4.trans per dnt give all 4 k-step B-fragments.
        const u32 va = vsm0 + s * 5120;
        #pragma unroll
        for (int dnt = 0; dnt < 4; dnt++) {
            u32 b00, b01, b10, b11, b20, b21, b30, b31;
            ldsm4t(b00, b01, b10, b11, va + dnt * 16);          // keys 0..31
            ldsm4t(b20, b21, b30, b31, va + dnt * 16 + 2560);   // keys 32..63
            mma_f16(oacc[dnt], pha[0][0], pha[0][1], pha[0][2], pha[0][3], b00, b01);
            mma_f16(oacc[dnt], pha[1][0], pha[1][1], pha[1][2], pha[1][3], b10, b11);
            mma_f16(oacc[dnt], pha[2][0], pha[2][1], pha[2][2], pha[2][3], b20, b21);
            mma_f16(oacc[dnt], pha[3][0], pha[3][1], pha[3][2], pha[3][3], b30, b31);
        }
        __syncthreads();
    }

    lA += __shfl_xor_sync(0xffffffffu, lA, 1);
    lA += __shfl_xor_sync(0xffffffffu, lA, 2);
    lB += __shfl_xor_sync(0xffffffffu, lB, 1);
    lB += __shfl_xor_sync(0xffffffffu, lB, 2);

    const float invA = 1.f / lA, invB = 1.f / lB;
    const long orow = (long)(b * NQ + q0 + wrp * 16 + gid);
    #pragma unroll
    for (int dnt = 0; dnt < 4; dnt++) {
        const int np = h * 16 + dnt * 4 + tig;          // kpair index 0..127
        const int kc = np >> 3, dp = np & 7;
        const int slot = (dp & 3) * 4 + (dp >> 2) * 2;
        u32 hh, ll;
        splith2(oacc[dnt][0] * invA, oacc[dnt][1] * invA, hh, ll);
        uint2 v0 = {hh, ll};
        *(uint2*)&g_ao[orow*256 + kc*16 + slot] = v0;
        splith2(oacc[dnt][2] * invB, oacc[dnt][3] * invB, hh, ll);
        uint2 v1 = {hh, ll};
        *(uint2*)&g_ao[(orow+8)*256 + kc*16 + slot] = v1;
    }
}

// ---------------------------------------------------------------------------
extern "C" void kernel_launch(void* const* d_in, const int* in_sizes, int n_in,
                              void* d_out, int out_size)
{
    const float* state = (const float*)d_in[0];
    const float* pc    = (const float*)d_in[1];
    const float* Wq    = (const float*)d_in[2];
    const float* bq    = (const float*)d_in[3];
    const float* Wkv   = (const float*)d_in[4];
    const float* bkv   = (const float*)d_in[5];
    const float* Wo    = (const float*)d_in[6];
    const float* bo    = (const float*)d_in[7];
    float* out = (float*)d_out;

    conv_act_all<<<(BB*NQ + BB*NK) * 32 / 256, 256>>>(state, pc);
    conv_w_all<<<dim3(32, 4), 256>>>(Wq, Wkv, Wo);

    gemm_hi<0, 1><<<dim3(DIMN/64,   BB*NQ/128), 256>>>(bq);
    gemm_hi<1, 2><<<dim3(2*DIMN/64, BB*NK/256), 256>>>(bkv);
    attn_mma<<<dim3(NQ/128, NHEAD, BB), 256>>>();
    gemm_o<<<dim3(DIMN/64, BB*NQ/128), 256>>>(bo, out);
}